// round 4
// baseline (speedup 1.0000x reference)
#include <cuda_runtime.h>
#include <cstdint>

#define H 768
#define NB 64
#define S1 513
#define S 512
#define NROWS (NB*S)   // 32768

// out layout (flattened tuple, float32):
// isqa_pred(64), crf_pred(32768), isqa_loss(1), crf_loss(1), tags(32768), IsQA(64)
#define OFF_ISQA_PRED 0
#define OFF_CRF_PRED  64
#define OFF_ISQA_LOSS (64+32768)
#define OFF_CRF_LOSS  (64+32768+1)
#define OFF_TAGS      (64+32768+2)
#define OFF_ISQA      (64+32768+2+32768)

__device__ __align__(16) float g_feats[NROWS*4 + 4];    // [b][s][4]
__device__ __align__(16) float g_featsT[NROWS*4 + 64];  // [s][b][4] transposed
// chunk-permuted exp(feats) for the partition scan:
// s in 1..511 stored at [b*512 + ((s-1)&15)*32 + ((s-1)>>4)]; slot 511 stays 0
__device__ __align__(16) float g_efeatsP[NROWS*4];
__device__ float g_logits[2*NB];
__device__ float g_Z[NB];
__device__ float g_gold[NB];

// ---------------------------------------------------------------------------
// K1: feats GEMV (blocks 0..1023, crfW in smem, double-buffered emb loads),
//     cls GEMV (1024..1031), tag/IsQA copy (1032..1039)
// ---------------------------------------------------------------------------
__global__ __launch_bounds__(256, 3) void k1(
    const float* __restrict__ emb, const int* __restrict__ asl,
    const int* __restrict__ isqa,
    const float* __restrict__ fc2W, const float* __restrict__ fc2b,
    const float* __restrict__ crfW, const float* __restrict__ crfb,
    float* __restrict__ out)
{
    const int bx = blockIdx.x;
    const int lane = threadIdx.x & 31;
    const int winb = threadIdx.x >> 5;

    if (bx < 1024) {
        __shared__ float4 ws[768];  // ws[t*192 + j] = crfW[t][4j..4j+3]
        for (int i = threadIdx.x; i < 768; i += 256)
            ws[i] = ((const float4*)crfW)[i];
        __syncthreads();

        const int warp = bx * 8 + winb;
        const int row0 = warp * 4;
        int base[4];
        #pragma unroll
        for (int r = 0; r < 4; r++) {
            const int row = row0 + r;
            const int b = row >> 9, s = row & 511;
            base[r] = (b * S1 + s + 1) * H;
        }
        float acc[4][4];
        #pragma unroll
        for (int r = 0; r < 4; r++)
            #pragma unroll
            for (int t = 0; t < 4; t++) acc[r][t] = 0.f;

        float4 ecur[4], enxt[4];
        #pragma unroll
        for (int r = 0; r < 4; r++)
            ecur[r] = __ldg((const float4*)&emb[base[r] + lane * 4]);

        #pragma unroll
        for (int k = 0; k < 6; k++) {
            if (k < 5) {
                #pragma unroll
                for (int r = 0; r < 4; r++)
                    enxt[r] = __ldg((const float4*)&emb[base[r] + (k + 1) * 128 + lane * 4]);
            }
            float4 w[4];
            #pragma unroll
            for (int t = 0; t < 4; t++)
                w[t] = ws[t * 192 + k * 32 + lane];
            #pragma unroll
            for (int r = 0; r < 4; r++)
                #pragma unroll
                for (int t = 0; t < 4; t++)
                    acc[r][t] += ecur[r].x * w[t].x + ecur[r].y * w[t].y
                               + ecur[r].z * w[t].z + ecur[r].w * w[t].w;
            #pragma unroll
            for (int r = 0; r < 4; r++) ecur[r] = enxt[r];
        }
        #pragma unroll
        for (int r = 0; r < 4; r++)
            #pragma unroll
            for (int t = 0; t < 4; t++) {
                float v = acc[r][t];
                v += __shfl_xor_sync(0xffffffffu, v, 16);
                v += __shfl_xor_sync(0xffffffffu, v, 8);
                v += __shfl_xor_sync(0xffffffffu, v, 4);
                v += __shfl_xor_sync(0xffffffffu, v, 2);
                v += __shfl_xor_sync(0xffffffffu, v, 1);
                acc[r][t] = v;
            }
        if (lane < 4) {
            const int row = row0 + lane;
            const int b = row >> 9, s = row & 511;
            float4 o;
            o.x = acc[lane][0] + crfb[0];
            o.y = acc[lane][1] + crfb[1];
            o.z = acc[lane][2] + crfb[2];
            o.w = acc[lane][3] + crfb[3];
            *(float4*)&g_feats[row * 4] = o;
            *(float4*)&g_featsT[(s * 64 + b) * 4] = o;
            if (s > 0) {
                const int p = ((s - 1) & 15) * 32 + ((s - 1) >> 4);
                float4 eo;
                eo.x = __expf(o.x); eo.y = __expf(o.y);
                eo.z = __expf(o.z); eo.w = __expf(o.w);
                *(float4*)&g_efeatsP[(b * 512 + p) * 4] = eo;
            }
        }
    } else if (bx < 1032) {
        // cls logits: warp per batch element
        const int b = (bx - 1024) * 8 + winb;
        float wa[6][4], wb[6][4];
        #pragma unroll
        for (int k = 0; k < 6; k++) {
            const int h = k * 128 + lane * 4;
            float4 va = *(const float4*)&fc2W[h];
            float4 vb = *(const float4*)&fc2W[H + h];
            wa[k][0] = va.x; wa[k][1] = va.y; wa[k][2] = va.z; wa[k][3] = va.w;
            wb[k][0] = vb.x; wb[k][1] = vb.y; wb[k][2] = vb.z; wb[k][3] = vb.w;
        }
        const int base = b * S1 * H;  // emb[:,0]
        float a0 = 0.f, a1 = 0.f;
        #pragma unroll
        for (int k = 0; k < 6; k++) {
            float4 e = __ldg((const float4*)&emb[base + k * 128 + lane * 4]);
            const float ec[4] = { e.x, e.y, e.z, e.w };
            #pragma unroll
            for (int c = 0; c < 4; c++) {
                a0 += ec[c] * wa[k][c];
                a1 += ec[c] * wb[k][c];
            }
        }
        #pragma unroll
        for (int o = 16; o > 0; o >>= 1) {
            a0 += __shfl_xor_sync(0xffffffffu, a0, o);
            a1 += __shfl_xor_sync(0xffffffffu, a1, o);
        }
        if (lane == 0) {
            g_logits[2 * b]     = a0 + fc2b[0];
            g_logits[2 * b + 1] = a1 + fc2b[1];
        }
    } else {
        // copies: tags + IsQA passthrough
        const int tid = (bx - 1032) * 256 + threadIdx.x;
        for (int i = tid; i < NROWS; i += 2048) {
            const int b = i >> 9, s = i & 511;
            out[OFF_TAGS + i] = (float)asl[b * S1 + 1 + s];
        }
        if (tid < NB) out[OFF_ISQA + tid] = (float)isqa[tid];
    }
}

// ---------------------------------------------------------------------------
// K2: bx 0,1  = viterbi, thread-per-batch (warp 0 only; 32 batches/warp),
//               coalesced g_featsT loads, smem bp + smem byte path + dump
//     bx 2..9 = log-partition (warp per batch, chunked semiring scan)
//     bx 10,11= gold score
// ---------------------------------------------------------------------------
__global__ __launch_bounds__(256) void k2(
    const int* __restrict__ asl, const float* __restrict__ trans,
    float* __restrict__ out)
{
    __shared__ uint32_t sbp[128 * 32];        // [chunk][lane], 4 bp bytes per word
    __shared__ unsigned char spathB[512 * 33];// [t][lane] padded stride 33

    const int bx = blockIdx.x;
    const int lane = threadIdx.x & 31;
    const int winb = threadIdx.x >> 5;

    if (bx < 2) {
        // ================= VITERBI (thread-per-batch) =================
        if (winb != 0) return;
        const int b = bx * 32 + lane;
        float T[16];
        #pragma unroll
        for (int i = 0; i < 16; i++) T[i] = trans[i];

        const float4* fT = (const float4*)g_featsT;
        float4 f0 = fT[b];  // s=0 row
        float d0 = f0.x + T[8], d1 = f0.y + T[9], d2 = f0.z + T[10], d3 = f0.w + T[11];

        #define VSTEP(f, byteref) {                                          \
            const float fa[4] = { (f).x, (f).y, (f).z, (f).w };              \
            float nd[4];                                                     \
            unsigned bwork = 0;                                              \
            _Pragma("unroll")                                                \
            for (int j = 0; j < 4; j++) {                                    \
                const float s0 = d0 + T[j],     s1 = d1 + T[4 + j];          \
                const float s2 = d2 + T[8 + j], s3 = d3 + T[12 + j];         \
                const float m01 = fmaxf(s0, s1);                             \
                const float m23 = fmaxf(s2, s3);                             \
                nd[j] = fmaxf(m01, m23) + fa[j];                             \
                const int bb = (m23 > m01) ? (2 + (int)(s3 > s2))            \
                                           : (int)(s1 > s0);                 \
                bwork |= (unsigned)bb << (2 * j);                            \
            }                                                                \
            d0 = nd[0]; d1 = nd[1]; d2 = nd[2]; d3 = nd[3];                  \
            (byteref) = bwork; }

        // 126 full chunks of 4 steps (s=1..504) + tail of 7 (s=505..511)
        float4 cur[4], nxt[4];
        #pragma unroll
        for (int u = 0; u < 4; u++) cur[u] = fT[(1 + u) * 64 + b];
        for (int c = 0; c < 126; c++) {
            #pragma unroll
            for (int u = 0; u < 4; u++) nxt[u] = fT[(c * 4 + 5 + u) * 64 + b];
            unsigned w = 0, byt;
            #pragma unroll
            for (int u = 0; u < 4; u++) {
                VSTEP(cur[u], byt);
                w |= byt << (8 * u);
            }
            sbp[c * 32 + lane] = w;
            #pragma unroll
            for (int u = 0; u < 4; u++) cur[u] = nxt[u];
        }
        {
            // tail: steps 505..511  (cur holds 505..508)
            float4 t3[3];
            #pragma unroll
            for (int u = 0; u < 3; u++) t3[u] = fT[(509 + u) * 64 + b];
            unsigned w = 0, byt;
            #pragma unroll
            for (int u = 0; u < 4; u++) { VSTEP(cur[u], byt); w |= byt << (8 * u); }
            sbp[126 * 32 + lane] = w;
            w = 0;
            #pragma unroll
            for (int u = 0; u < 3; u++) { VSTEP(t3[u], byt); w |= byt << (8 * u); }
            sbp[127 * 32 + lane] = w;
        }
        #undef VSTEP

        const float s0 = d0 + T[3], s1 = d1 + T[7], s2 = d2 + T[11], s3 = d3 + T[15];
        float mm = s0; int tag = 0;
        if (s1 > mm) { mm = s1; tag = 1; }
        if (s2 > mm) { mm = s2; tag = 2; }
        if (s3 > mm) { mm = s3; tag = 3; }
        spathB[511 * 33 + lane] = (unsigned char)tag;
        // backtrace: bp word for chunk c covers steps 4c+1..4c+4; byte for
        // step s updates tag -> path[s-1]
        for (int c = 127; c >= 0; c--) {
            const unsigned w = sbp[c * 32 + lane];
            #pragma unroll
            for (int u = 3; u >= 0; u--) {
                const int s = c * 4 + 1 + u;
                if (s > 511) continue;
                const unsigned byte = (w >> (8 * u)) & 0xffu;
                tag = (byte >> (2 * tag)) & 3;
                spathB[(s - 1) * 33 + lane] = (unsigned char)tag;
            }
        }
        __syncwarp();
        // coalesced dump: for each batch column, lanes sweep t
        for (int q = 0; q < 32; q++) {
            const int bb = q;  // local batch column
            float* dst = out + OFF_CRF_PRED + (bx * 32 + bb) * 512;
            #pragma unroll
            for (int r = 0; r < 16; r++) {
                const int t = r * 32 + lane;
                dst[t] = (float)spathB[t * 33 + bb];
            }
        }
    } else if (bx < 10) {
        // ================= PARTITION (chunked linear-domain scan) ==========
        const int b = (bx - 2) * 8 + winb;
        float E[4][4];
        #pragma unroll
        for (int i = 0; i < 4; i++)
            #pragma unroll
            for (int j = 0; j < 4; j++) E[i][j] = expf(trans[i * 4 + j]);

        const float4* eb = (const float4*)g_efeatsP + b * 512;
        float m[16];     // transfer matrix, row-major [i][j]
        float lg = 0.f;  // log of factored-out scale

        #define RENORM() {                                                   \
            float mx = m[0];                                                 \
            _Pragma("unroll")                                                \
            for (int q = 1; q < 16; q++) mx = fmaxf(mx, m[q]);               \
            const float inv = __fdividef(1.f, mx);                           \
            _Pragma("unroll")                                                \
            for (int q = 0; q < 16; q++) m[q] *= inv;                        \
            lg += __logf(mx); }

        #define MSTEP(e4) {                                                  \
            const float ee[4] = { (e4).x, (e4).y, (e4).z, (e4).w };          \
            float nm[16];                                                    \
            _Pragma("unroll")                                                \
            for (int i = 0; i < 4; i++)                                      \
                _Pragma("unroll")                                            \
                for (int j = 0; j < 4; j++)                                  \
                    nm[i*4+j] = ((m[i*4+0]*E[0][j] + m[i*4+1]*E[1][j])       \
                               + (m[i*4+2]*E[2][j] + m[i*4+3]*E[3][j])) * ee[j]; \
            _Pragma("unroll")                                                \
            for (int q = 0; q < 16; q++) m[q] = nm[q]; }

        {
            float4 ld[8];
            #pragma unroll
            for (int u = 0; u < 8; u++) ld[u] = eb[u * 32 + lane];
            #pragma unroll
            for (int i = 0; i < 4; i++) {
                m[i*4+0] = E[i][0] * ld[0].x;
                m[i*4+1] = E[i][1] * ld[0].y;
                m[i*4+2] = E[i][2] * ld[0].z;
                m[i*4+3] = E[i][3] * ld[0].w;
            }
            #pragma unroll
            for (int u = 1; u < 8; u++) MSTEP(ld[u]);
            RENORM();
            #pragma unroll
            for (int u = 0; u < 8; u++) ld[u] = eb[(u + 8) * 32 + lane];
            #pragma unroll
            for (int u = 8; u < 16; u++) {
                if (lane < 31 || u < 15) MSTEP(ld[u - 8]);
            }
            RENORM();
        }
        #pragma unroll
        for (int off = 1; off < 32; off <<= 1) {
            float pm[16], plg;
            #pragma unroll
            for (int q = 0; q < 16; q++)
                pm[q] = __shfl_up_sync(0xffffffffu, m[q], off);
            plg = __shfl_up_sync(0xffffffffu, lg, off);
            if (lane >= off) {
                float nm[16];
                #pragma unroll
                for (int i = 0; i < 4; i++)
                    #pragma unroll
                    for (int j = 0; j < 4; j++)
                        nm[i*4+j] = ((pm[i*4+0]*m[0*4+j] + pm[i*4+1]*m[1*4+j])
                                   + (pm[i*4+2]*m[2*4+j] + pm[i*4+3]*m[3*4+j]));
                #pragma unroll
                for (int q = 0; q < 16; q++) m[q] = nm[q];
                lg += plg;
                RENORM();
            }
        }
        if (lane == 31) {
            float4 f0 = *(const float4*)&g_feats[b * 2048];
            const float x0 = f0.x + trans[8],  x1 = f0.y + trans[9];
            const float x2 = f0.z + trans[10], x3 = f0.w + trans[11];
            const float m0 = fmaxf(fmaxf(x0, x1), fmaxf(x2, x3));
            const float a0 = __expf(x0 - m0), a1 = __expf(x1 - m0);
            const float a2 = __expf(x2 - m0), a3 = __expf(x3 - m0);
            float z = 0.f;
            #pragma unroll
            for (int j = 0; j < 4; j++) {
                const float vj = a0 * m[0*4+j] + a1 * m[1*4+j]
                               + a2 * m[2*4+j] + a3 * m[3*4+j];
                z += vj * E[j][3];
            }
            g_Z[b] = m0 + lg + __logf(z);
        }
        #undef MSTEP
        #undef RENORM
    } else {
        // ================= GOLD =================
        const int wg = (bx - 10) * 8 + winb;
        for (int q = 0; q < 4; q++) {
            const int b = wg * 4 + q;
            float s = 0.f;
            for (int i = lane; i < 512; i += 32) {
                const int tg = asl[b * S1 + 1 + i];
                s += g_feats[(b * 512 + i) * 4 + tg];
                if (i < 511) {
                    const int tg2 = asl[b * S1 + 2 + i];
                    s += trans[tg * 4 + tg2];
                }
            }
            if (lane == 0) {
                const int t0 = asl[b * S1 + 1];
                const int tl = asl[b * S1 + 512];
                s += trans[8 + t0] + trans[tl * 4 + 3];
            }
            #pragma unroll
            for (int o = 16; o > 0; o >>= 1) s += __shfl_xor_sync(0xffffffffu, s, o);
            if (lane == 0) g_gold[b] = s;
        }
    }
}

// ---------------------------------------------------------------------------
// K3: losses + isqa predictions
// ---------------------------------------------------------------------------
__global__ void k3(const int* __restrict__ isqa, float* __restrict__ out)
{
    __shared__ float sh[4];
    const int t = threadIdx.x;  // 64 threads
    float diff = 0.f, lossb = 0.f;
    if (t < NB) {
        diff = g_Z[t] - g_gold[t];
        const float l0 = g_logits[2 * t], l1 = g_logits[2 * t + 1];
        const float m = fmaxf(l0, l1);
        const float lse = m + __logf(__expf(l0 - m) + __expf(l1 - m));
        const int q = isqa[t];
        lossb = lse - (q ? l1 : l0);
        out[OFF_ISQA_PRED + t] = (l1 > l0) ? 1.0f : 0.0f;
    }
    #pragma unroll
    for (int o = 16; o > 0; o >>= 1) {
        diff  += __shfl_xor_sync(0xffffffffu, diff, o);
        lossb += __shfl_xor_sync(0xffffffffu, lossb, o);
    }
    if ((t & 31) == 0) { sh[(t >> 5) * 2] = diff; sh[(t >> 5) * 2 + 1] = lossb; }
    __syncthreads();
    if (t == 0) {
        out[OFF_CRF_LOSS]  = (sh[0] + sh[2]) * (1.0f / 64.0f);
        out[OFF_ISQA_LOSS] = (sh[1] + sh[3]) * (1.0f / 64.0f);
    }
}

extern "C" void kernel_launch(void* const* d_in, const int* in_sizes, int n_in,
                              void* d_out, int out_size)
{
    const float* emb  = (const float*)d_in[0];
    const int*   asl  = (const int*)d_in[1];
    const int*   isqa = (const int*)d_in[2];
    const float* fc2W = (const float*)d_in[3];
    const float* fc2b = (const float*)d_in[4];
    const float* crfW = (const float*)d_in[5];
    const float* crfb = (const float*)d_in[6];
    const float* trans= (const float*)d_in[7];
    float* out = (float*)d_out;

    k1<<<1040, 256>>>(emb, asl, isqa, fc2W, fc2b, crfW, crfb, out);
    k2<<<12, 256>>>(asl, trans, out);
    k3<<<1, 64>>>(isqa, out);
}

// round 9
// speedup vs baseline: 1.3282x; 1.3282x over previous
#include <cuda_runtime.h>
#include <cstdint>

#define H 768
#define NB 64
#define S1 513
#define S 512
#define NROWS (NB*S)   // 32768

// out layout (flattened tuple, float32):
// isqa_pred(64), crf_pred(32768), isqa_loss(1), crf_loss(1), tags(32768), IsQA(64)
#define OFF_ISQA_PRED 0
#define OFF_CRF_PRED  64
#define OFF_ISQA_LOSS (64+32768)
#define OFF_CRF_LOSS  (64+32768+1)
#define OFF_TAGS      (64+32768+2)
#define OFF_ISQA      (64+32768+2+32768)

__device__ __align__(16) float g_feats[NROWS*4 + 4];    // [b][s][4]
__device__ __align__(16) float g_featsT[NROWS*4 + 64];  // [s][b][4] transposed
// chunk-permuted exp(feats) for the partition scan:
// s in 1..511 stored at [b*512 + ((s-1)&15)*32 + ((s-1)>>4)]; slot 511 stays 0
__device__ __align__(16) float g_efeatsP[NROWS*4];
__device__ float g_logits[2*NB];
__device__ float g_Z[NB];
__device__ float g_gold[NB];

// ---------------------------------------------------------------------------
// K1: feats GEMV (blocks 0..1023, crfW in smem, double-buffered emb loads),
//     cls GEMV (1024..1031), tag/IsQA copy (1032..1039)
// ---------------------------------------------------------------------------
__global__ __launch_bounds__(256, 3) void k1(
    const float* __restrict__ emb, const int* __restrict__ asl,
    const int* __restrict__ isqa,
    const float* __restrict__ fc2W, const float* __restrict__ fc2b,
    const float* __restrict__ crfW, const float* __restrict__ crfb,
    float* __restrict__ out)
{
    const int bx = blockIdx.x;
    const int lane = threadIdx.x & 31;
    const int winb = threadIdx.x >> 5;

    if (bx < 1024) {
        __shared__ float4 ws[768];  // ws[t*192 + j] = crfW[t][4j..4j+3]
        for (int i = threadIdx.x; i < 768; i += 256)
            ws[i] = ((const float4*)crfW)[i];
        __syncthreads();

        const int row0 = (bx * 8 + winb) * 4;
        const int b0 = row0 >> 9, s0 = row0 & 511;   // 4 rows share batch b0
        const int base0 = (b0 * S1 + s0 + 1) * H;
        float acc[4][4];
        #pragma unroll
        for (int r = 0; r < 4; r++)
            #pragma unroll
            for (int t = 0; t < 4; t++) acc[r][t] = 0.f;

        float4 ecur[4], enxt[4];
        #pragma unroll
        for (int r = 0; r < 4; r++)
            ecur[r] = __ldg((const float4*)&emb[base0 + r * H + lane * 4]);

        #pragma unroll
        for (int k = 0; k < 6; k++) {
            if (k < 5) {
                #pragma unroll
                for (int r = 0; r < 4; r++)
                    enxt[r] = __ldg((const float4*)&emb[base0 + r * H + (k + 1) * 128 + lane * 4]);
            }
            float4 w[4];
            #pragma unroll
            for (int t = 0; t < 4; t++)
                w[t] = ws[t * 192 + k * 32 + lane];
            #pragma unroll
            for (int r = 0; r < 4; r++)
                #pragma unroll
                for (int t = 0; t < 4; t++)
                    acc[r][t] += ecur[r].x * w[t].x + ecur[r].y * w[t].y
                               + ecur[r].z * w[t].z + ecur[r].w * w[t].w;
            #pragma unroll
            for (int r = 0; r < 4; r++) ecur[r] = enxt[r];
        }
        #pragma unroll
        for (int r = 0; r < 4; r++)
            #pragma unroll
            for (int t = 0; t < 4; t++) {
                float v = acc[r][t];
                v += __shfl_xor_sync(0xffffffffu, v, 16);
                v += __shfl_xor_sync(0xffffffffu, v, 8);
                v += __shfl_xor_sync(0xffffffffu, v, 4);
                v += __shfl_xor_sync(0xffffffffu, v, 2);
                v += __shfl_xor_sync(0xffffffffu, v, 1);
                acc[r][t] = v;
            }
        if (lane < 4) {
            const int row = row0 + lane;
            const int b = b0, s = s0 + lane;
            float4 o;
            o.x = acc[lane][0] + crfb[0];
            o.y = acc[lane][1] + crfb[1];
            o.z = acc[lane][2] + crfb[2];
            o.w = acc[lane][3] + crfb[3];
            *(float4*)&g_feats[row * 4] = o;
            *(float4*)&g_featsT[(s * 64 + b) * 4] = o;
            if (s > 0) {
                const int p = ((s - 1) & 15) * 32 + ((s - 1) >> 4);
                float4 eo;
                eo.x = __expf(o.x); eo.y = __expf(o.y);
                eo.z = __expf(o.z); eo.w = __expf(o.w);
                *(float4*)&g_efeatsP[(b * 512 + p) * 4] = eo;
            }
        }
    } else if (bx < 1032) {
        // cls logits: warp per batch element
        const int b = (bx - 1024) * 8 + winb;
        float wa[6][4], wb[6][4];
        #pragma unroll
        for (int k = 0; k < 6; k++) {
            const int h = k * 128 + lane * 4;
            float4 va = *(const float4*)&fc2W[h];
            float4 vb = *(const float4*)&fc2W[H + h];
            wa[k][0] = va.x; wa[k][1] = va.y; wa[k][2] = va.z; wa[k][3] = va.w;
            wb[k][0] = vb.x; wb[k][1] = vb.y; wb[k][2] = vb.z; wb[k][3] = vb.w;
        }
        const int base = b * S1 * H;  // emb[:,0]
        float a0 = 0.f, a1 = 0.f;
        #pragma unroll
        for (int k = 0; k < 6; k++) {
            float4 e = __ldg((const float4*)&emb[base + k * 128 + lane * 4]);
            const float ec[4] = { e.x, e.y, e.z, e.w };
            #pragma unroll
            for (int c = 0; c < 4; c++) {
                a0 += ec[c] * wa[k][c];
                a1 += ec[c] * wb[k][c];
            }
        }
        #pragma unroll
        for (int o = 16; o > 0; o >>= 1) {
            a0 += __shfl_xor_sync(0xffffffffu, a0, o);
            a1 += __shfl_xor_sync(0xffffffffu, a1, o);
        }
        if (lane == 0) {
            g_logits[2 * b]     = a0 + fc2b[0];
            g_logits[2 * b + 1] = a1 + fc2b[1];
        }
    } else {
        // copies: tags + IsQA passthrough
        const int tid = (bx - 1032) * 256 + threadIdx.x;
        for (int i = tid; i < NROWS; i += 2048) {
            const int b = i >> 9, s = i & 511;
            out[OFF_TAGS + i] = (float)asl[b * S1 + 1 + s];
        }
        if (tid < NB) out[OFF_ISQA + tid] = (float)isqa[tid];
    }
}

// ---------------------------------------------------------------------------
// K2: bx 0,1   = viterbi, thread-per-batch, 2-chunk-deep pipelined loads
//     bx 2..9  = log-partition (warp per batch, chunked semiring scan)
//     bx 10..17= gold score (warp per batch, batched two-wave loads)
// ---------------------------------------------------------------------------
__global__ __launch_bounds__(256) void k2(
    const int* __restrict__ asl, const float* __restrict__ trans,
    float* __restrict__ out)
{
    __shared__ uint32_t sbp[128 * 32];         // [2*chunk + w][lane]
    __shared__ unsigned char spathB[512 * 33]; // [t][lane] padded stride 33
    __shared__ float strans[16];

    const int bx = blockIdx.x;
    const int lane = threadIdx.x & 31;
    const int winb = threadIdx.x >> 5;

    if (bx < 2) {
        // ================= VITERBI (thread-per-batch) =================
        if (winb != 0) return;
        const int b = bx * 32 + lane;
        float T[16];
        #pragma unroll
        for (int i = 0; i < 16; i++) T[i] = trans[i];

        const float4* fT = (const float4*)g_featsT;
        float4 f0 = fT[b];  // s=0 row
        float d0 = f0.x + T[8], d1 = f0.y + T[9], d2 = f0.z + T[10], d3 = f0.w + T[11];

        #define VSTEP(f, byteref) {                                          \
            const float fa[4] = { (f).x, (f).y, (f).z, (f).w };              \
            float nd[4];                                                     \
            unsigned bwork = 0;                                              \
            _Pragma("unroll")                                                \
            for (int j = 0; j < 4; j++) {                                    \
                const float s0 = d0 + T[j],     s1 = d1 + T[4 + j];          \
                const float s2 = d2 + T[8 + j], s3 = d3 + T[12 + j];         \
                const float m01 = fmaxf(s0, s1);                             \
                const float m23 = fmaxf(s2, s3);                             \
                nd[j] = fmaxf(m01, m23) + fa[j];                             \
                const int bb = (m23 > m01) ? (2 + (int)(s3 > s2))            \
                                           : (int)(s1 > s0);                 \
                bwork |= (unsigned)bb << (2 * j);                            \
            }                                                                \
            d0 = nd[0]; d1 = nd[1]; d2 = nd[2]; d3 = nd[3];                  \
            (byteref) = bwork; }

        #define VCOMPUTE(buf, c) {                                           \
            unsigned w0 = 0, w1 = 0, byt;                                    \
            _Pragma("unroll")                                                \
            for (int u = 0; u < 4; u++) { VSTEP(buf[u], byt); w0 |= byt << (8*u); } \
            _Pragma("unroll")                                                \
            for (int u = 4; u < 8; u++) { VSTEP(buf[u], byt); w1 |= byt << (8*(u-4)); } \
            sbp[(2*(c))*32 + lane] = w0;                                     \
            sbp[(2*(c)+1)*32 + lane] = w1; }

        #define VLOAD(buf, c) {                                              \
            const int vc = ((c) < 62 ? (c) : 62);                            \
            _Pragma("unroll")                                                \
            for (int u = 0; u < 8; u++) buf[u] = fT[(vc*8 + 1 + u)*64 + b]; }

        // full chunks c=0..62 cover s=1..504; tail C covers s=505..511
        float4 A[8], B[8], C[7];
        #pragma unroll
        for (int u = 0; u < 8; u++) A[u] = fT[(1 + u) * 64 + b];
        #pragma unroll
        for (int u = 0; u < 8; u++) B[u] = fT[(9 + u) * 64 + b];
        #pragma unroll
        for (int u = 0; u < 7; u++) C[u] = fT[(505 + u) * 64 + b];

        #pragma unroll 1
        for (int cc = 0; cc < 31; cc++) {
            VCOMPUTE(A, 2 * cc);     VLOAD(A, 2 * cc + 2);
            VCOMPUTE(B, 2 * cc + 1); VLOAD(B, 2 * cc + 3);
        }
        VCOMPUTE(A, 62);
        {   // tail chunk c=63: 7 steps
            unsigned w0 = 0, w1 = 0, byt;
            #pragma unroll
            for (int u = 0; u < 4; u++) { VSTEP(C[u], byt); w0 |= byt << (8*u); }
            #pragma unroll
            for (int u = 4; u < 7; u++) { VSTEP(C[u], byt); w1 |= byt << (8*(u-4)); }
            sbp[126 * 32 + lane] = w0;
            sbp[127 * 32 + lane] = w1;
        }
        #undef VSTEP
        #undef VCOMPUTE
        #undef VLOAD

        const float s0 = d0 + T[3], s1 = d1 + T[7], s2 = d2 + T[11], s3 = d3 + T[15];
        float mm = s0; int tag = 0;
        if (s1 > mm) { mm = s1; tag = 1; }
        if (s2 > mm) { mm = s2; tag = 2; }
        if (s3 > mm) { mm = s3; tag = 3; }
        spathB[511 * 33 + lane] = (unsigned char)tag;
        // backtrace: byte for step s=8c+1+u updates tag -> path[s-1]
        #pragma unroll 1
        for (int c = 63; c >= 0; c--) {
            const unsigned w0 = sbp[(2*c)*32 + lane];
            const unsigned w1 = sbp[(2*c+1)*32 + lane];
            #pragma unroll
            for (int u = 7; u >= 4; u--) {
                const int s = c * 8 + 1 + u;
                if (s > 511) continue;
                const unsigned byte = (w1 >> (8 * (u - 4))) & 0xffu;
                tag = (byte >> (2 * tag)) & 3;
                spathB[(s - 1) * 33 + lane] = (unsigned char)tag;
            }
            #pragma unroll
            for (int u = 3; u >= 0; u--) {
                const int s = c * 8 + 1 + u;
                const unsigned byte = (w0 >> (8 * u)) & 0xffu;
                tag = (byte >> (2 * tag)) & 3;
                spathB[(s - 1) * 33 + lane] = (unsigned char)tag;
            }
        }
        __syncwarp();
        // coalesced dump: for each batch column, lanes sweep t
        for (int q = 0; q < 32; q++) {
            float* dst = out + OFF_CRF_PRED + (bx * 32 + q) * 512;
            #pragma unroll
            for (int r = 0; r < 16; r++) {
                const int t = r * 32 + lane;
                dst[t] = (float)spathB[t * 33 + q];
            }
        }
    } else if (bx < 10) {
        // ================= PARTITION (chunked linear-domain scan) ==========
        const int b = (bx - 2) * 8 + winb;
        float E[4][4];
        #pragma unroll
        for (int i = 0; i < 4; i++)
            #pragma unroll
            for (int j = 0; j < 4; j++) E[i][j] = expf(trans[i * 4 + j]);

        const float4* eb = (const float4*)g_efeatsP + b * 512;
        float m[16];     // transfer matrix, row-major [i][j]
        float lg = 0.f;  // log of factored-out scale

        #define RENORM() {                                                   \
            float mx = m[0];                                                 \
            _Pragma("unroll")                                                \
            for (int q = 1; q < 16; q++) mx = fmaxf(mx, m[q]);               \
            const float inv = __fdividef(1.f, mx);                           \
            _Pragma("unroll")                                                \
            for (int q = 0; q < 16; q++) m[q] *= inv;                        \
            lg += __logf(mx); }

        #define MSTEP(e4) {                                                  \
            const float ee[4] = { (e4).x, (e4).y, (e4).z, (e4).w };          \
            float nm[16];                                                    \
            _Pragma("unroll")                                                \
            for (int i = 0; i < 4; i++)                                      \
                _Pragma("unroll")                                            \
                for (int j = 0; j < 4; j++)                                  \
                    nm[i*4+j] = ((m[i*4+0]*E[0][j] + m[i*4+1]*E[1][j])       \
                               + (m[i*4+2]*E[2][j] + m[i*4+3]*E[3][j])) * ee[j]; \
            _Pragma("unroll")                                                \
            for (int q = 0; q < 16; q++) m[q] = nm[q]; }

        {
            float4 ld[8];
            #pragma unroll
            for (int u = 0; u < 8; u++) ld[u] = eb[u * 32 + lane];
            #pragma unroll
            for (int i = 0; i < 4; i++) {
                m[i*4+0] = E[i][0] * ld[0].x;
                m[i*4+1] = E[i][1] * ld[0].y;
                m[i*4+2] = E[i][2] * ld[0].z;
                m[i*4+3] = E[i][3] * ld[0].w;
            }
            #pragma unroll
            for (int u = 1; u < 8; u++) MSTEP(ld[u]);
            RENORM();
            #pragma unroll
            for (int u = 0; u < 8; u++) ld[u] = eb[(u + 8) * 32 + lane];
            #pragma unroll
            for (int u = 8; u < 16; u++) {
                if (lane < 31 || u < 15) MSTEP(ld[u - 8]);
            }
            RENORM();
        }
        #pragma unroll
        for (int off = 1; off < 32; off <<= 1) {
            float pm[16], plg;
            #pragma unroll
            for (int q = 0; q < 16; q++)
                pm[q] = __shfl_up_sync(0xffffffffu, m[q], off);
            plg = __shfl_up_sync(0xffffffffu, lg, off);
            if (lane >= off) {
                float nm[16];
                #pragma unroll
                for (int i = 0; i < 4; i++)
                    #pragma unroll
                    for (int j = 0; j < 4; j++)
                        nm[i*4+j] = ((pm[i*4+0]*m[0*4+j] + pm[i*4+1]*m[1*4+j])
                                   + (pm[i*4+2]*m[2*4+j] + pm[i*4+3]*m[3*4+j]));
                #pragma unroll
                for (int q = 0; q < 16; q++) m[q] = nm[q];
                lg += plg;
                RENORM();
            }
        }
        if (lane == 31) {
            float4 f0 = *(const float4*)&g_feats[b * 2048];
            const float x0 = f0.x + trans[8],  x1 = f0.y + trans[9];
            const float x2 = f0.z + trans[10], x3 = f0.w + trans[11];
            const float m0 = fmaxf(fmaxf(x0, x1), fmaxf(x2, x3));
            const float a0 = __expf(x0 - m0), a1 = __expf(x1 - m0);
            const float a2 = __expf(x2 - m0), a3 = __expf(x3 - m0);
            float z = 0.f;
            #pragma unroll
            for (int j = 0; j < 4; j++) {
                const float vj = a0 * m[0*4+j] + a1 * m[1*4+j]
                               + a2 * m[2*4+j] + a3 * m[3*4+j];
                z += vj * E[j][3];
            }
            g_Z[b] = m0 + lg + __logf(z);
        }
        #undef MSTEP
        #undef RENORM
    } else {
        // ================= GOLD (warp per batch, two-wave batched loads) ===
        if (threadIdx.x < 16) strans[threadIdx.x] = trans[threadIdx.x];
        __syncthreads();
        const int b = (bx - 10) * 8 + winb;
        const int abase = b * S1 + 1 + lane * 16;
        int tg[16];
        #pragma unroll
        for (int u = 0; u < 16; u++) tg[u] = asl[abase + u];
        float s = 0.f;
        #pragma unroll
        for (int u = 0; u < 16; u++)
            s += g_feats[((b << 9) + lane * 16 + u) * 4 + tg[u]];
        // transitions: 15 local pairs + cross-lane pair via shfl
        const int tnext0 = __shfl_down_sync(0xffffffffu, tg[0], 1);
        #pragma unroll
        for (int u = 0; u < 15; u++)
            s += strans[tg[u] * 4 + tg[u + 1]];
        if (lane < 31) s += strans[tg[15] * 4 + tnext0];
        if (lane == 0)  s += strans[8 + tg[0]];
        if (lane == 31) s += strans[tg[15] * 4 + 3];
        #pragma unroll
        for (int o = 16; o > 0; o >>= 1) s += __shfl_xor_sync(0xffffffffu, s, o);
        if (lane == 0) g_gold[b] = s;
    }
}

// ---------------------------------------------------------------------------
// K3: losses + isqa predictions
// ---------------------------------------------------------------------------
__global__ void k3(const int* __restrict__ isqa, float* __restrict__ out)
{
    __shared__ float sh[4];
    const int t = threadIdx.x;  // 64 threads
    float diff = 0.f, lossb = 0.f;
    if (t < NB) {
        diff = g_Z[t] - g_gold[t];
        const float l0 = g_logits[2 * t], l1 = g_logits[2 * t + 1];
        const float m = fmaxf(l0, l1);
        const float lse = m + __logf(__expf(l0 - m) + __expf(l1 - m));
        const int q = isqa[t];
        lossb = lse - (q ? l1 : l0);
        out[OFF_ISQA_PRED + t] = (l1 > l0) ? 1.0f : 0.0f;
    }
    #pragma unroll
    for (int o = 16; o > 0; o >>= 1) {
        diff  += __shfl_xor_sync(0xffffffffu, diff, o);
        lossb += __shfl_xor_sync(0xffffffffu, lossb, o);
    }
    if ((t & 31) == 0) { sh[(t >> 5) * 2] = diff; sh[(t >> 5) * 2 + 1] = lossb; }
    __syncthreads();
    if (t == 0) {
        out[OFF_CRF_LOSS]  = (sh[0] + sh[2]) * (1.0f / 64.0f);
        out[OFF_ISQA_LOSS] = (sh[1] + sh[3]) * (1.0f / 64.0f);
    }
}

extern "C" void kernel_launch(void* const* d_in, const int* in_sizes, int n_in,
                              void* d_out, int out_size)
{
    const float* emb  = (const float*)d_in[0];
    const int*   asl  = (const int*)d_in[1];
    const int*   isqa = (const int*)d_in[2];
    const float* fc2W = (const float*)d_in[3];
    const float* fc2b = (const float*)d_in[4];
    const float* crfW = (const float*)d_in[5];
    const float* crfb = (const float*)d_in[6];
    const float* trans= (const float*)d_in[7];
    float* out = (float*)d_out;

    k1<<<1040, 256>>>(emb, asl, isqa, fc2W, fc2b, crfW, crfb, out);
    k2<<<18, 256>>>(asl, trans, out);
    k3<<<1, 64>>>(isqa, out);
}